// round 5
// baseline (speedup 1.0000x reference)
#include <cuda_runtime.h>
#include <math.h>
#include <stdint.h>

#define B_ 2
#define S_ 4096
#define D_ 768
#define H_ 12
#define DK_ 64

// scratch (no cudaMalloc allowed)
__device__ float g_Q[(size_t)B_ * S_ * D_];
__device__ float g_K[(size_t)B_ * S_ * D_];
__device__ float g_V[(size_t)B_ * S_ * D_];
__device__ float g_AO[(size_t)B_ * S_ * D_];
__device__ float g_T[(size_t)3 * B_ * S_ * D_];   // pre-rounded+permuted inputs
__device__ float g_W4[(size_t)4 * D_ * D_];       // pre-rounded+permuted weights

__device__ __forceinline__ uint32_t f2tf(float x) {
    uint32_t u;
    asm("cvt.rna.tf32.f32 %0, %1;" : "=r"(u) : "f"(x));
    return u;
}
__device__ __forceinline__ float fex2(float x) {
    float y;
    asm("ex2.approx.f32 %0, %1;" : "=f"(y) : "f"(x));
    return y;
}

__device__ __forceinline__ void mma8(float* c, const uint32_t* a,
                                     uint32_t b0, uint32_t b1) {
    asm volatile(
        "mma.sync.aligned.m16n8k8.row.col.f32.tf32.tf32.f32 "
        "{%0,%1,%2,%3}, {%4,%5,%6,%7}, {%8,%9}, {%0,%1,%2,%3};"
        : "+f"(c[0]), "+f"(c[1]), "+f"(c[2]), "+f"(c[3])
        : "r"(a[0]), "r"(a[1]), "r"(a[2]), "r"(a[3]), "r"(b0), "r"(b1));
}

__device__ __forceinline__ void cpa16(uint32_t saddr, const void* g) {
    asm volatile("cp.async.cg.shared.global [%0], [%1], 16;"
                 :: "r"(saddr), "l"(g));
}
__device__ __forceinline__ uint32_t cvs(const void* p) {
    return (uint32_t)__cvta_generic_to_shared(p);
}
#define CPCOMMIT asm volatile("cp.async.commit_group;")
#define CPWAIT0  asm volatile("cp.async.wait_group 0;")

// ---------------------------------------------------------------------------
// pre-round to tf32 AND permute within 8-elem groups of last dim:
// out[2*(k&3)+(k>>2)] = in[k]  ->  out = {in0,in4,in1,in5,in2,in6,in3,in7}
// ---------------------------------------------------------------------------
__global__ void preround_perm(const float* __restrict__ src,
                              float* __restrict__ dst, int n8) {
    int i = blockIdx.x * blockDim.x + threadIdx.x;
    if (i < n8) {
        float4 lo = ((const float4*)src)[2 * i];
        float4 hi = ((const float4*)src)[2 * i + 1];
        uint4 o0, o1;
        o0.x = f2tf(lo.x); o0.y = f2tf(hi.x); o0.z = f2tf(lo.y); o0.w = f2tf(hi.y);
        o1.x = f2tf(lo.z); o1.y = f2tf(hi.z); o1.z = f2tf(lo.w); o1.w = f2tf(hi.w);
        ((uint4*)dst)[2 * i] = o0;
        ((uint4*)dst)[2 * i + 1] = o1;
    }
}

// ---------------------------------------------------------------------------
// TC GEMM on pre-rounded, k-permuted operands: C = A @ W^T + bias.
// MODE 0: raw out; 1: tf32 out; 2: tf32(out * 0.125*log2e) (Q prescale).
// PERMN: permute output cols within 8-groups (for Q/K head-dim fragments).
// ---------------------------------------------------------------------------
template <int MODE, int PERMN>
__global__ void __launch_bounds__(256) gemm_pre(const float* __restrict__ A,
                                                const float* __restrict__ W,
                                                const float* __restrict__ bias,
                                                float* __restrict__ C,
                                                int M, int N, int K) {
    extern __shared__ float sg[];
    float* Asb[2] = { sg,        sg + 4352 };
    float* Wsb[2] = { sg + 8704, sg + 13056 };

    const int tid = threadIdx.x, lane = tid & 31, w = tid >> 5;
    const int mw = w >> 1, nw = w & 1, g = lane >> 2, t = lane & 3;
    const int m0 = blockIdx.x * 64, n0 = blockIdx.y * 64;

    float acc[4][4] = {};

#define GSTAGE(k0, bufi)                                                       \
    {                                                                          \
        _Pragma("unroll")                                                      \
        for (int r = 0; r < 4; r++) {                                          \
            int idx = tid + r * 256, rr = idx >> 4, cc = idx & 15;             \
            cpa16(cvs(&Asb[bufi][rr * 68 + cc * 4]),                           \
                  &A[(size_t)(m0 + rr) * K + (k0) + cc * 4]);                  \
            cpa16(cvs(&Wsb[bufi][rr * 68 + cc * 4]),                           \
                  &W[(size_t)(n0 + rr) * K + (k0) + cc * 4]);                  \
        }                                                                      \
    }

    GSTAGE(0, 0); CPCOMMIT;
    const int NT = K / 64;
    for (int kt = 0; kt < NT; kt++) {
        CPWAIT0;
        __syncthreads();
        if (kt + 1 < NT) { GSTAGE((kt + 1) * 64, (kt + 1) & 1); CPCOMMIT; }
        const uint32_t* Au = (const uint32_t*)Asb[kt & 1];
        const uint32_t* Wu = (const uint32_t*)Wsb[kt & 1];
#pragma unroll
        for (int k8 = 0; k8 < 8; k8++) {
            int ar = (mw * 16 + g) * 68 + 2 * t + 8 * k8;
            uint2 a02 = *(const uint2*)&Au[ar];
            uint2 a13 = *(const uint2*)&Au[ar + 8 * 68];
            uint32_t a[4] = { a02.x, a13.x, a02.y, a13.y };
#pragma unroll
            for (int nf = 0; nf < 4; nf++) {
                int br = (nw * 32 + nf * 8 + g) * 68 + 2 * t + 8 * k8;
                uint2 b = *(const uint2*)&Wu[br];
                mma8(acc[nf], a, b.x, b.y);
            }
        }
    }

    const float QSC = 0.125f * 1.44269504f;
    int mrow = m0 + mw * 16 + g;
#pragma unroll
    for (int nf = 0; nf < 4; nf++) {
        int base8 = n0 + nw * 32 + nf * 8;
        int n = base8 + 2 * t;
        float b0 = bias[n], b1 = bias[n + 1];
        float v0 = acc[nf][0] + b0, v1 = acc[nf][1] + b1;
        float v2 = acc[nf][2] + b0, v3 = acc[nf][3] + b1;
        if (MODE == 1) {
            v0 = __uint_as_float(f2tf(v0)); v1 = __uint_as_float(f2tf(v1));
            v2 = __uint_as_float(f2tf(v2)); v3 = __uint_as_float(f2tf(v3));
        } else if (MODE == 2) {
            v0 = __uint_as_float(f2tf(v0 * QSC));
            v1 = __uint_as_float(f2tf(v1 * QSC));
            v2 = __uint_as_float(f2tf(v2 * QSC));
            v3 = __uint_as_float(f2tf(v3 * QSC));
        }
        if (PERMN) {
            int p0 = base8 + (t & 1) * 4 + (t >> 1);  // perm(2t)
            C[(size_t)mrow * N + p0] = v0;
            C[(size_t)mrow * N + p0 + 2] = v1;        // perm(2t+1)=perm(2t)+2
            C[(size_t)(mrow + 8) * N + p0] = v2;
            C[(size_t)(mrow + 8) * N + p0 + 2] = v3;
        } else {
            *(float2*)&C[(size_t)mrow * N + n] = make_float2(v0, v1);
            *(float2*)&C[(size_t)(mrow + 8) * N + n] = make_float2(v2, v3);
        }
    }
}

// ---------------------------------------------------------------------------
// TC flash attention, 2 passes, no-max softmax (exp2 form), cp.async pipe.
// Q pre-scaled by 0.125*log2e; Q/K head-dim permuted -> LDS64 fragments.
// ---------------------------------------------------------------------------
#define STRK 68
#define STRV 72

__global__ void __launch_bounds__(256, 2)
attn_tc(const float* __restrict__ Qg, const float* __restrict__ Kg,
        const float* __restrict__ Vg, float* __restrict__ Pout,
        float* __restrict__ Oout) {
    extern __shared__ float sm[];
    float* Ksb[2] = { sm,                 sm + 64 * STRK };
    float* Vsb[2] = { sm + 2 * 64 * STRK, sm + 2 * 64 * STRK + 64 * STRV };
    float* Qs = sm + 2 * 64 * STRK + 2 * 64 * STRV;  // 4608 floats (Q / P tile)
    uint2* PT = (uint2*)Qs;                          // P: [col*36 + pair]
    float* Ls = Qs + 4608;                           // 256 floats
    const uint32_t* Qu = (const uint32_t*)Qs;

    const int tid = threadIdx.x, lane = tid & 31, w = tid >> 5;
    const int mw = w & 1, nw = w >> 1, g = lane >> 2, t = lane & 3;
    const int q0 = blockIdx.x * 64, h = blockIdx.y, b = blockIdx.z;
    const size_t qbase = ((size_t)b * S_ + q0) * D_ + h * DK_;
    const size_t kvbase = (size_t)b * S_ * D_ + h * DK_;

#define KSTAGE(jt, bufi)                                                       \
    {                                                                          \
        _Pragma("unroll")                                                      \
        for (int r = 0; r < 4; r++) {                                          \
            int idx = tid + r * 256, rr = idx >> 4, cc = idx & 15;             \
            cpa16(cvs(&Ksb[bufi][rr * STRK + cc * 4]),                         \
                  &Kg[kvbase + (size_t)((jt) * 64 + rr) * D_ + cc * 4]);       \
        }                                                                      \
    }
#define VSTAGE(jt, bufi)                                                       \
    {                                                                          \
        _Pragma("unroll")                                                      \
        for (int r = 0; r < 4; r++) {                                          \
            int idx = tid + r * 256, rr = idx >> 4, cc = idx & 15;             \
            cpa16(cvs(&Vsb[bufi][rr * STRV + cc * 4]),                         \
                  &Vg[kvbase + (size_t)((jt) * 64 + rr) * D_ + cc * 4]);       \
        }                                                                      \
    }

    // stage Q (tf32, scaled, k-permuted); pull A-fragments via LDS64
#pragma unroll
    for (int r = 0; r < 4; r++) {
        int idx = tid + r * 256, rr = idx >> 4, cc = idx & 15;
        *(float4*)&Qs[rr * 68 + cc * 4] =
            *(const float4*)&Qg[qbase + (size_t)rr * D_ + cc * 4];
    }
    __syncthreads();
    uint32_t qa[2][8][4];
#pragma unroll
    for (int mm = 0; mm < 2; mm++) {
        int ar = (mw * 32 + mm * 16 + g) * 68 + 2 * t;
#pragma unroll
        for (int k8 = 0; k8 < 8; k8++) {
            uint2 q02 = *(const uint2*)&Qu[ar + 8 * k8];
            uint2 q13 = *(const uint2*)&Qu[ar + 8 * 68 + 8 * k8];
            qa[mm][k8][0] = q02.x; qa[mm][k8][1] = q13.x;
            qa[mm][k8][2] = q02.y; qa[mm][k8][3] = q13.y;
        }
    }

    // ---------------- pass 1: rowsums of exp2(scores') ----------------
    KSTAGE(0, 0); CPCOMMIT;
    float ls[2][2] = {};
    for (int jt = 0; jt < S_ / 64; jt++) {
        CPWAIT0;
        __syncthreads();
        if (jt + 1 < S_ / 64) { KSTAGE(jt + 1, (jt + 1) & 1); CPCOMMIT; }
        const uint32_t* Ku = (const uint32_t*)Ksb[jt & 1];
        float c[2][2][4] = {};
#pragma unroll
        for (int k8 = 0; k8 < 8; k8++) {
#pragma unroll
            for (int nf = 0; nf < 2; nf++) {
                int br = (nw * 16 + nf * 8 + g) * STRK + 2 * t + 8 * k8;
                uint2 bb = *(const uint2*)&Ku[br];
                mma8(c[0][nf], qa[0][k8], bb.x, bb.y);
                mma8(c[1][nf], qa[1][k8], bb.x, bb.y);
            }
        }
#pragma unroll
        for (int mm = 0; mm < 2; mm++)
#pragma unroll
            for (int nf = 0; nf < 2; nf++) {
                ls[mm][0] += fex2(c[mm][nf][0]) + fex2(c[mm][nf][1]);
                ls[mm][1] += fex2(c[mm][nf][2]) + fex2(c[mm][nf][3]);
            }
    }
#pragma unroll
    for (int mm = 0; mm < 2; mm++)
#pragma unroll
        for (int hh = 0; hh < 2; hh++) {
            ls[mm][hh] += __shfl_xor_sync(~0u, ls[mm][hh], 1);
            ls[mm][hh] += __shfl_xor_sync(~0u, ls[mm][hh], 2);
        }
    if (t == 0) {
#pragma unroll
        for (int mm = 0; mm < 2; mm++) {
            Ls[nw * 64 + mw * 32 + mm * 16 + g]     = ls[mm][0];
            Ls[nw * 64 + mw * 32 + mm * 16 + 8 + g] = ls[mm][1];
        }
    }
    KSTAGE(0, 0); VSTAGE(0, 0); CPCOMMIT;
    __syncthreads();
    float linv[2][2];
#pragma unroll
    for (int mm = 0; mm < 2; mm++) {
        int r0 = mw * 32 + mm * 16 + g;
        linv[mm][0] = 1.f / (Ls[r0] + Ls[64 + r0] + Ls[128 + r0] + Ls[192 + r0]);
        int r1 = r0 + 8;
        linv[mm][1] = 1.f / (Ls[r1] + Ls[64 + r1] + Ls[128 + r1] + Ls[192 + r1]);
    }
    __syncthreads();  // Qs fragments consumed; PT region now owned by pass 2

    // ---------------- pass 2: P out + P@V ----------------
    float out[2][2][4] = {};
    for (int jt = 0; jt < S_ / 64; jt++) {
        CPWAIT0;
        __syncthreads();
        if (jt + 1 < S_ / 64) {
            KSTAGE(jt + 1, (jt + 1) & 1); VSTAGE(jt + 1, (jt + 1) & 1); CPCOMMIT;
        }
        const uint32_t* Ku = (const uint32_t*)Ksb[jt & 1];
        const uint32_t* Vu = (const uint32_t*)Vsb[jt & 1];
        float c[2][2][4] = {};
#pragma unroll
        for (int k8 = 0; k8 < 8; k8++) {
#pragma unroll
            for (int nf = 0; nf < 2; nf++) {
                int br = (nw * 16 + nf * 8 + g) * STRK + 2 * t + 8 * k8;
                uint2 bb = *(const uint2*)&Ku[br];
                mma8(c[0][nf], qa[0][k8], bb.x, bb.y);
                mma8(c[1][nf], qa[1][k8], bb.x, bb.y);
            }
        }
        // normalized P -> gmem; tf32 P -> transposed row-pair smem tile
#pragma unroll
        for (int mm = 0; mm < 2; mm++) {
            int rowg = mw * 32 + mm * 16 + g;
            int pi = 16 * mw + 8 * mm + g;
            size_t gp = ((size_t)(b * H_ + h) * S_ + (q0 + rowg)) * S_ +
                        jt * 64 + nw * 16 + 2 * t;
#pragma unroll
            for (int nf = 0; nf < 2; nf++) {
                float p0 = fex2(c[mm][nf][0]) * linv[mm][0];
                float p1 = fex2(c[mm][nf][1]) * linv[mm][0];
                float p2 = fex2(c[mm][nf][2]) * linv[mm][1];
                float p3 = fex2(c[mm][nf][3]) * linv[mm][1];
                *(float2*)&Pout[gp + nf * 8] = make_float2(p0, p1);
                *(float2*)&Pout[gp + nf * 8 + (size_t)8 * S_] = make_float2(p2, p3);
                int c0 = nw * 16 + nf * 8 + 2 * t;
                PT[c0 * 36 + pi] = make_uint2(f2tf(p0), f2tf(p2));
                PT[(c0 + 1) * 36 + pi] = make_uint2(f2tf(p1), f2tf(p3));
            }
        }
        __syncthreads();
        // P @ V  (pa via conflict-free LDS64)
#pragma unroll
        for (int k8 = 0; k8 < 8; k8++) {
            int ca = t + 8 * k8, cb = ca + 4;
            uint2 u0 = PT[ca * 36 + 16 * mw + g];
            uint2 u1 = PT[cb * 36 + 16 * mw + g];
            uint2 u2 = PT[ca * 36 + 16 * mw + 8 + g];
            uint2 u3 = PT[cb * 36 + 16 * mw + 8 + g];
            uint32_t pa0[4] = { u0.x, u0.y, u1.x, u1.y };
            uint32_t pa1[4] = { u2.x, u2.y, u3.x, u3.y };
#pragma unroll
            for (int nf = 0; nf < 2; nf++) {
                int n = nw * 16 + nf * 8 + g;
                uint32_t b0 = Vu[(8 * k8 + t) * STRV + n];
                uint32_t b1 = Vu[(8 * k8 + t + 4) * STRV + n];
                mma8(out[0][nf], pa0, b0, b1);
                mma8(out[1][nf], pa1, b0, b1);
            }
        }
        __syncthreads();
    }

    // epilogue: AO in [B,S,D], tf32-rounded AND feature-permuted for O-GEMM
#pragma unroll
    for (int mm = 0; mm < 2; mm++) {
        int row = q0 + mw * 32 + mm * 16 + g;
#pragma unroll
        for (int nf = 0; nf < 2; nf++) {
            int base8 = h * DK_ + nw * 16 + nf * 8;
            int p0 = base8 + (t & 1) * 4 + (t >> 1);  // perm(2t)
            size_t r0 = ((size_t)b * S_ + row) * D_;
            size_t r1 = ((size_t)b * S_ + row + 8) * D_;
            Oout[r0 + p0]     = __uint_as_float(f2tf(out[mm][nf][0]));
            Oout[r0 + p0 + 2] = __uint_as_float(f2tf(out[mm][nf][1]));
            Oout[r1 + p0]     = __uint_as_float(f2tf(out[mm][nf][2]));
            Oout[r1 + p0 + 2] = __uint_as_float(f2tf(out[mm][nf][3]));
        }
    }
}

// ---------------------------------------------------------------------------
extern "C" void kernel_launch(void* const* d_in, const int* in_sizes, int n_in,
                              void* d_out, int out_size) {
    const float* query = (const float*)d_in[0];
    const float* key   = (const float*)d_in[1];
    const float* value = (const float*)d_in[2];
    const float* Wq = (const float*)d_in[3];
    const float* bq = (const float*)d_in[4];
    const float* Wk = (const float*)d_in[5];
    const float* bk = (const float*)d_in[6];
    const float* Wv = (const float*)d_in[7];
    const float* bv = (const float*)d_in[8];
    const float* Wo = (const float*)d_in[9];
    const float* bo = (const float*)d_in[10];

    float* out_main = (float*)d_out;
    float* out_attn = (float*)d_out + (size_t)B_ * S_ * D_;

    float* Qp;  cudaGetSymbolAddress((void**)&Qp, g_Q);
    float* Kp;  cudaGetSymbolAddress((void**)&Kp, g_K);
    float* Vp;  cudaGetSymbolAddress((void**)&Vp, g_V);
    float* AOp; cudaGetSymbolAddress((void**)&AOp, g_AO);
    float* Tp;  cudaGetSymbolAddress((void**)&Tp, g_T);
    float* Wp;  cudaGetSymbolAddress((void**)&Wp, g_W4);

    const size_t NX = (size_t)B_ * S_ * D_;   // 6291456
    const size_t NW = (size_t)D_ * D_;        // 589824

    preround_perm<<<(int)(NX / 8 + 255) / 256, 256>>>(query, Tp, (int)(NX / 8));
    preround_perm<<<(int)(NX / 8 + 255) / 256, 256>>>(key,   Tp + NX, (int)(NX / 8));
    preround_perm<<<(int)(NX / 8 + 255) / 256, 256>>>(value, Tp + 2 * NX, (int)(NX / 8));
    preround_perm<<<(int)(NW / 8 + 255) / 256, 256>>>(Wq, Wp, (int)(NW / 8));
    preround_perm<<<(int)(NW / 8 + 255) / 256, 256>>>(Wk, Wp + NW, (int)(NW / 8));
    preround_perm<<<(int)(NW / 8 + 255) / 256, 256>>>(Wv, Wp + 2 * NW, (int)(NW / 8));
    preround_perm<<<(int)(NW / 8 + 255) / 256, 256>>>(Wo, Wp + 3 * NW, (int)(NW / 8));

    const int M = B_ * S_;
    dim3 pg(M / 64, D_ / 64);
    const int gsmem = 4 * 4352 * 4;
    cudaFuncSetAttribute(gemm_pre<2, 1>,
                         cudaFuncAttributeMaxDynamicSharedMemorySize, gsmem);
    cudaFuncSetAttribute(gemm_pre<1, 1>,
                         cudaFuncAttributeMaxDynamicSharedMemorySize, gsmem);
    cudaFuncSetAttribute(gemm_pre<1, 0>,
                         cudaFuncAttributeMaxDynamicSharedMemorySize, gsmem);
    cudaFuncSetAttribute(gemm_pre<0, 0>,
                         cudaFuncAttributeMaxDynamicSharedMemorySize, gsmem);
    const int asmem = (2 * 64 * STRK + 2 * 64 * STRV + 4608 + 256) * 4;  // 91136 B
    cudaFuncSetAttribute(attn_tc,
                         cudaFuncAttributeMaxDynamicSharedMemorySize, asmem);

    gemm_pre<2, 1><<<pg, 256, gsmem>>>(Tp,          Wp,          bq, Qp, M, D_, D_);
    gemm_pre<1, 1><<<pg, 256, gsmem>>>(Tp + NX,     Wp + NW,     bk, Kp, M, D_, D_);
    gemm_pre<1, 0><<<pg, 256, gsmem>>>(Tp + 2 * NX, Wp + 2 * NW, bv, Vp, M, D_, D_);

    attn_tc<<<dim3(S_ / 64, H_, B_), 256, asmem>>>(Qp, Kp, Vp, out_attn, AOp);

    gemm_pre<0, 0><<<pg, 256, gsmem>>>(AOp, Wp + 3 * NW, bo, out_main, M, D_, D_);
}